// round 7
// baseline (speedup 1.0000x reference)
#include <cuda_runtime.h>
#include <math.h>

#define VOLD   256
#define NGAUSS 4000
// Tile shape 4 x 8 x 16 (x,y,z): 32 (x,y) rows -> 32 lanes; 64B z-row stores.
#define TSX 4
#define TSY 8
#define TSZ 16
#define NTX 64
#define NTY 32
#define NTZ 16
#define NTILES (NTX * NTY * NTZ)      // 32768
#define CAP    32
#define SLICE  28                     // wx[4] wy[8] wz[16]

// ---------------------------------------------------------------------------
// Static device scratch. Zeroed at module load; gather self-cleans g_cnt each
// launch, so the invariant holds across correctness run, capture, and replays.
// ---------------------------------------------------------------------------
__device__ int g_cnt[NTILES];
__device__ __align__(16) float g_slice[(size_t)NTILES * CAP * SLICE];

// ---------------------------------------------------------------------------
// Kernel 1: block per Gaussian. Threads 0..95 compute the 3x32 separable
// weight window. Then cooperative pair scatter: each warp handles 4 pairs per
// iteration; 7 lanes per pair write one contiguous 112B slice (1 STG.128 per
// lane), group leader does the atomicAdd, slot broadcast by shfl.
// ---------------------------------------------------------------------------
__global__ __launch_bounds__(128) void prep_kernel(
    const float* __restrict__ centers,
    const float* __restrict__ sigmas,
    const float* __restrict__ intens)
{
    const int g = blockIdx.x;
    const int t = threadIdx.x;
    const int warp = t >> 5;
    const int lane = t & 31;

    __shared__ float sw[3][32];
    __shared__ int s_tmin[3], s_tn[3], s_start[3];

    const float sig    = sigmas[g];
    const float inv2s2 = 0.5f / (sig * sig);
    const float I      = intens[g];
    const float cut    = 3.0f * sig * 255.0f;

    if (t < 96) {
        const int axis = t >> 5;
        const int o    = t & 31;

        const float cn = centers[3 * g + axis];
        const float cv = cn * 255.0f;

        const float minf = fmaxf(cv - cut, 0.0f);
        const float maxf = fminf(cv + cut, 255.0f);
        const int   mini = (int)floorf(minf);
        const int   maxi = min((int)floorf(maxf) + 1, VOLD);   // exclusive
        const int   start = min(mini, VOLD - 32);

        const int idx = start + o;
        float w = 0.0f;
        if (idx >= mini && idx < maxi) {
            const float d = (float)idx * (1.0f / 255.0f) - cn;
            w = expf(-d * d * inv2s2);
        }
        if (axis == 0) w *= I;
        sw[axis][o] = w;

        if (o == 0) {
            const int shf  = (axis == 0) ? 2 : ((axis == 1) ? 3 : 4);
            const int tmin = mini >> shf;
            const int tmax = (maxi - 1) >> shf;
            s_tmin[axis]  = tmin;
            s_tn[axis]    = tmax - tmin + 1;
            s_start[axis] = start;
        }
    }
    __syncthreads();

    const int x0 = s_tmin[0], y0 = s_tmin[1], z0 = s_tmin[2];
    const int nx = s_tn[0],   ny = s_tn[1],   nz = s_tn[2];
    const int st0 = s_start[0], st1 = s_start[1], st2 = s_start[2];
    const int total = nx * ny * nz;

    const int group = lane / 7;             // 0..3 active, 4 = idle lanes 28-31
    const int j     = lane - group * 7;     // float4 index within slice

    for (int chunk = 0; chunk < total; chunk += 16) {
        const int p = chunk + warp * 4 + group;
        const bool valid = (group < 4) && (p < total);

        int tile = 0, k0 = 0, k1 = 0, k2 = 0;
        if (valid) {
            const int iz = p % nz;
            const int r  = p / nz;
            const int iy = r % ny;
            const int ix = r / ny;
            const int tx = x0 + ix, ty = y0 + iy, tz = z0 + iz;
            tile = (tx * NTY + ty) * NTZ + tz;
            k0 = (tx << 2) - st0;
            k1 = (ty << 3) - st1;
            k2 = (tz << 4) - st2;
        }

        int my = -1;
        if (valid && j == 0) my = atomicAdd(&g_cnt[tile], 1);
        const int slot = __shfl_sync(0xffffffffu, my, group * 7);

        if (valid && (unsigned)slot < (unsigned)CAP) {
            int axis, kb;
            if (j == 0)      { axis = 0; kb = k0; }
            else if (j < 3)  { axis = 1; kb = k1 + 4 * (j - 1); }
            else             { axis = 2; kb = k2 + 4 * (j - 3); }
            float4 v;
            v.x = ((unsigned)(kb + 0) < 32u) ? sw[axis][kb + 0] : 0.f;
            v.y = ((unsigned)(kb + 1) < 32u) ? sw[axis][kb + 1] : 0.f;
            v.z = ((unsigned)(kb + 2) < 32u) ? sw[axis][kb + 2] : 0.f;
            v.w = ((unsigned)(kb + 3) < 32u) ? sw[axis][kb + 3] : 0.f;
            float* dst = g_slice + ((size_t)tile * CAP + slot) * SLICE + j * 4;
            *(float4*)dst = v;
        }
    }
}

// ---------------------------------------------------------------------------
// Kernel 2: gather, warp-persistent: each warp processes exactly 4 tiles
// (grid 1024 x 256, 8192 warps, 32768 tiles). Inner loop uses packed
// fma.rn.f32x2 (bit-identical rounding to scalar fmaf).
// ---------------------------------------------------------------------------
__global__ __launch_bounds__(256, 5) void gather_kernel(float* __restrict__ vol) {
    const int warpL = threadIdx.x >> 5;
    const int lane  = threadIdx.x & 31;
    const int gwarp = blockIdx.x * 8 + warpL;
    const int NW    = gridDim.x * 8;

    __shared__ __align__(16) float sh[8][CAP * SLICE];   // 28 KB

    const int x = lane >> 3;              // 0..3
    const int y = lane & 7;               // 0..7
    const float* __restrict__ swp = sh[warpL];

    for (int tile = gwarp; tile < NTILES; tile += NW) {
        const int cnt = min(g_cnt[tile], CAP);

        // Coalesced warp stage: cnt*7 contiguous float4s
        const float4* __restrict__ src =
            (const float4*)(g_slice + (size_t)tile * CAP * SLICE);
        float4* shv = (float4*)swp;
        for (int i = lane; i < cnt * (SLICE / 4); i += 32) shv[i] = src[i];
        __syncwarp();
        if (lane == 0) g_cnt[tile] = 0;   // restore invariant for next launch

        unsigned long long acc[8];
#pragma unroll
        for (int i = 0; i < 8; ++i) acc[i] = 0ull;

#pragma unroll 4
        for (int p = 0; p < cnt; ++p) {
            const float* s = swp + p * SLICE;
            const float f = s[x] * s[4 + y];
            unsigned long long ff;
            asm("mov.b64 %0, {%1, %1};" : "=l"(ff) : "r"(__float_as_uint(f)));
            const ulonglong2* wz = (const ulonglong2*)(s + 12);
#pragma unroll
            for (int q = 0; q < 4; ++q) {
                const ulonglong2 w = wz[q];
                asm("fma.rn.f32x2 %0, %1, %2, %0;"
                    : "+l"(acc[2 * q])     : "l"(w.x), "l"(ff));
                asm("fma.rn.f32x2 %0, %1, %2, %0;"
                    : "+l"(acc[2 * q + 1]) : "l"(w.y), "l"(ff));
            }
        }
        __syncwarp();                     // shared reuse safe next iteration

        const int tzi = tile & (NTZ - 1);
        const int tyi = (tile >> 4) & (NTY - 1);
        const int txi = tile >> 9;
        float* out = vol + ((size_t)(txi * TSX + x) * VOLD + (tyi * TSY + y)) * VOLD
                         + tzi * TSZ;
#pragma unroll
        for (int q = 0; q < 4; ++q) {
            ulonglong2 o;
            o.x = acc[2 * q];
            o.y = acc[2 * q + 1];
            *(ulonglong2*)(out + 4 * q) = o;
        }
    }
}

// ---------------------------------------------------------------------------
extern "C" void kernel_launch(void* const* d_in, const int* in_sizes, int n_in,
                              void* d_out, int out_size) {
    const float* centers = (const float*)d_in[0];
    const float* sigmas  = (const float*)d_in[1];
    const float* intens  = (const float*)d_in[2];
    float* vol = (float*)d_out;

    prep_kernel<<<NGAUSS, 128>>>(centers, sigmas, intens);
    gather_kernel<<<1024, 256>>>(vol);
}

// round 8
// speedup vs baseline: 1.0922x; 1.0922x over previous
#include <cuda_runtime.h>
#include <math.h>

#define VOLD   256
#define NGAUSS 4000
// Tile shape 4 x 8 x 16 (x,y,z): 32 (x,y) rows -> 32 lanes; 64B z-row stores.
#define TSX 4
#define TSY 8
#define TSZ 16
#define NTX 64
#define NTY 32
#define NTZ 16
#define NTILES (NTX * NTY * NTZ)      // 32768
#define CAP    32
#define SLICE  28                     // wx[4] wy[8] wz[16]
#define MAXP   128                    // max pairs per gaussian (true max 120)

// ---------------------------------------------------------------------------
// Static device scratch. Zeroed at module load; gather self-cleans g_cnt each
// launch, so the invariant holds across correctness run, capture, and replays.
// ---------------------------------------------------------------------------
__device__ int g_cnt[NTILES];
__device__ __align__(16) float g_slice[(size_t)NTILES * CAP * SLICE];

// ---------------------------------------------------------------------------
// Kernel 1: block per Gaussian. Phase A: threads 0..95 compute the 3x32
// separable window (one exp each). Phase B: thread-per-pair -> slice into
// SHARED (+ atomic slot). Phase C: block-coalesced scalar copy shared->global
// (consecutive lanes write consecutive floats of the same slice).
// ---------------------------------------------------------------------------
__global__ __launch_bounds__(128) void prep_kernel(
    const float* __restrict__ centers,
    const float* __restrict__ sigmas,
    const float* __restrict__ intens)
{
    const int g = blockIdx.x;
    const int t = threadIdx.x;

    __shared__ float sw[3][32];
    __shared__ int s_tmin[3], s_tn[3], s_start[3];
    __shared__ float sl[MAXP][29];          // 29: bank-conflict-free stride
    __shared__ long long sdst[MAXP];        // float offset into g_slice, -1 invalid

    const float sig    = sigmas[g];
    const float inv2s2 = 0.5f / (sig * sig);
    const float I      = intens[g];
    const float cut    = 3.0f * sig * 255.0f;

    if (t < 96) {
        const int axis = t >> 5;
        const int o    = t & 31;

        const float cn = centers[3 * g + axis];
        const float cv = cn * 255.0f;

        const float minf = fmaxf(cv - cut, 0.0f);
        const float maxf = fminf(cv + cut, 255.0f);
        const int   mini = (int)floorf(minf);
        const int   maxi = min((int)floorf(maxf) + 1, VOLD);   // exclusive
        const int   start = min(mini, VOLD - 32);

        const int idx = start + o;
        float w = 0.0f;
        if (idx >= mini && idx < maxi) {
            const float d = (float)idx * (1.0f / 255.0f) - cn;
            w = expf(-d * d * inv2s2);
        }
        if (axis == 0) w *= I;
        sw[axis][o] = w;

        if (o == 0) {
            const int shf  = (axis == 0) ? 2 : ((axis == 1) ? 3 : 4);
            const int tmin = mini >> shf;
            const int tmax = (maxi - 1) >> shf;
            s_tmin[axis]  = tmin;
            s_tn[axis]    = tmax - tmin + 1;
            s_start[axis] = start;
        }
    }
    __syncthreads();

    const int nx = s_tn[0], ny = s_tn[1], nz = s_tn[2];
    const int total = nx * ny * nz;        // <= 120

    // Phase B: one pair per thread
    if (t < total) {
        const int iz = t % nz;
        const int r  = t / nz;
        const int iy = r % ny;
        const int ix = r / ny;
        const int tx = s_tmin[0] + ix, ty = s_tmin[1] + iy, tz = s_tmin[2] + iz;
        const int tile = (tx * NTY + ty) * NTZ + tz;

        const int slot = atomicAdd(&g_cnt[tile], 1);
        if (slot < CAP) {
            sdst[t] = ((long long)tile * CAP + slot) * SLICE;
            const int k0 = (tx << 2) - s_start[0];
            const int k1 = (ty << 3) - s_start[1];
            const int k2 = (tz << 4) - s_start[2];
#pragma unroll
            for (int j = 0; j < 4; ++j) {
                const int k = k0 + j;
                sl[t][j] = ((unsigned)k < 32u) ? sw[0][k] : 0.f;
            }
#pragma unroll
            for (int j = 0; j < 8; ++j) {
                const int k = k1 + j;
                sl[t][4 + j] = ((unsigned)k < 32u) ? sw[1][k] : 0.f;
            }
#pragma unroll
            for (int j = 0; j < 16; ++j) {
                const int k = k2 + j;
                sl[t][12 + j] = ((unsigned)k < 32u) ? sw[2][k] : 0.f;
            }
        } else {
            sdst[t] = -1;
        }
    }
    __syncthreads();

    // Phase C: coalesced scalar copy to global
    const int nel = total * SLICE;
    for (int i = t; i < nel; i += 128) {
        const int p = i / SLICE;
        const int j = i - p * SLICE;
        const long long d = sdst[p];
        if (d >= 0) g_slice[d + j] = sl[p][j];
    }
}

// ---------------------------------------------------------------------------
// Kernel 2: gather, warp-persistent (exactly 4 tiles per warp), cp.async
// double-buffered staging; counter prefetch 2 tiles ahead. Lane = (x,y) row;
// 16-voxel z row in registers; 4 contiguous float4 stores per tile.
// ---------------------------------------------------------------------------
__device__ __forceinline__ void stage_tile(float4* dst_sh, const float4* src,
                                           int n4, int lane) {
    unsigned s = (unsigned)__cvta_generic_to_shared(dst_sh);
    for (int i = lane; i < n4; i += 32)
        asm volatile("cp.async.ca.shared.global [%0], [%1], 16;"
                     :: "r"(s + i * 16), "l"(src + i));
}

__global__ __launch_bounds__(128) void gather_kernel(float* __restrict__ vol) {
    const int warpL = threadIdx.x >> 5;
    const int lane  = threadIdx.x & 31;
    const int gw    = blockIdx.x * 4 + warpL;       // 0..8191
    const int NW    = 8192;

    __shared__ __align__(16) float4 buf[4][2][CAP * 7];   // 28 KB

    const int x = lane >> 3;
    const int y = lane & 7;

    int tiles[4], cnt[4];
#pragma unroll
    for (int k = 0; k < 4; ++k) tiles[k] = gw + k * NW;

    cnt[0] = g_cnt[tiles[0]];
    cnt[1] = g_cnt[tiles[1]];
    cnt[0] = min(cnt[0], CAP);

    stage_tile(buf[warpL][0],
               (const float4*)(g_slice + (size_t)tiles[0] * CAP * SLICE),
               cnt[0] * 7, lane);
    asm volatile("cp.async.commit_group;");

#pragma unroll
    for (int k = 0; k < 4; ++k) {
        if (k + 2 < 4) cnt[k + 2] = g_cnt[tiles[k + 2]];
        if (k + 1 < 4) {
            cnt[k + 1] = min(cnt[k + 1], CAP);
            stage_tile(buf[warpL][(k + 1) & 1],
                       (const float4*)(g_slice + (size_t)tiles[k + 1] * CAP * SLICE),
                       cnt[k + 1] * 7, lane);
            asm volatile("cp.async.commit_group;");
            asm volatile("cp.async.wait_group 1;");
        } else {
            asm volatile("cp.async.wait_group 0;");
        }
        __syncwarp();
        if (lane == 0) g_cnt[tiles[k]] = 0;   // restore invariant for next launch

        const float* __restrict__ s0 = (const float*)buf[warpL][k & 1];
        const int c = cnt[k];

        float a[16];
#pragma unroll
        for (int i = 0; i < 16; ++i) a[i] = 0.f;

#pragma unroll 4
        for (int p = 0; p < c; ++p) {
            const float* s = s0 + p * SLICE;
            const float f = s[x] * s[4 + y];
#pragma unroll
            for (int q = 0; q < 4; ++q) {
                const float4 wz = *(const float4*)(s + 12 + 4 * q);
                a[4*q+0] = fmaf(f, wz.x, a[4*q+0]);
                a[4*q+1] = fmaf(f, wz.y, a[4*q+1]);
                a[4*q+2] = fmaf(f, wz.z, a[4*q+2]);
                a[4*q+3] = fmaf(f, wz.w, a[4*q+3]);
            }
        }
        __syncwarp();                         // all lanes done reading buffer

        const int tl  = tiles[k];
        const int tzi = tl & (NTZ - 1);
        const int tyi = (tl >> 4) & (NTY - 1);
        const int txi = tl >> 9;
        float* out = vol + ((size_t)(txi * TSX + x) * VOLD + (tyi * TSY + y)) * VOLD
                         + tzi * TSZ;
#pragma unroll
        for (int q = 0; q < 4; ++q)
            *(float4*)(out + 4 * q) =
                make_float4(a[4*q+0], a[4*q+1], a[4*q+2], a[4*q+3]);
    }
}

// ---------------------------------------------------------------------------
extern "C" void kernel_launch(void* const* d_in, const int* in_sizes, int n_in,
                              void* d_out, int out_size) {
    const float* centers = (const float*)d_in[0];
    const float* sigmas  = (const float*)d_in[1];
    const float* intens  = (const float*)d_in[2];
    float* vol = (float*)d_out;

    prep_kernel<<<NGAUSS, 128>>>(centers, sigmas, intens);
    gather_kernel<<<2048, 128>>>(vol);
}